// round 5
// baseline (speedup 1.0000x reference)
#include <cuda_runtime.h>
#include <math.h>
#include <stdint.h>

// ---------------- problem constants ----------------
#define DDIM 512
#define TSTEPS 1024
#define BATCH 8
#define NSLOT 32
#define CPB 16            // CTAs per batch == cluster size
#define SLICE 32          // d-slice per CTA
#define MROWS (BATCH*TSTEPS)
#define SCAN_THREADS 512

// ---------------- static device scratch ----------------
__device__ float g_xproj[(size_t)MROWS * DDIM];
__device__ float g_siluz[(size_t)MROWS * DDIM];
__device__ float g_xw   [(size_t)MROWS * DDIM];
__device__ float g_hs   [(size_t)MROWS * DDIM];

__device__ __forceinline__ float siluf(float v) { return v / (1.0f + __expf(-v)); }

// ---------------- cluster / mbarrier helpers ----------------
__device__ __forceinline__ uint32_t smem_u32(const void* p) {
    return (uint32_t)__cvta_generic_to_shared(p);
}
__device__ __forceinline__ void mbar_init(uint32_t a, uint32_t cnt) {
    asm volatile("mbarrier.init.shared.b64 [%0], %1;" :: "r"(a), "r"(cnt) : "memory");
}
__device__ __forceinline__ uint32_t mapa_u32(uint32_t a, uint32_t rank) {
    uint32_t r;
    asm volatile("mapa.shared::cluster.u32 %0, %1, %2;" : "=r"(r) : "r"(a), "r"(rank));
    return r;
}
// FIXED: explicit cluster-scope RELEASE so the preceding st.shared::cluster
// stores are published to the peer that acquires on this barrier.
__device__ __forceinline__ void mbar_arrive_cluster(uint32_t a) {
    asm volatile("mbarrier.arrive.release.cluster.shared::cluster.b64 _, [%0];"
                 :: "r"(a) : "memory");
}
__device__ __forceinline__ void st_cluster_f4(uint32_t addr, float4 v) {
    asm volatile("st.shared::cluster.v4.f32 [%0], {%1,%2,%3,%4};"
                 :: "r"(addr), "f"(v.x), "f"(v.y), "f"(v.z), "f"(v.w) : "memory");
}
__device__ __forceinline__ void mbar_wait(uint32_t a, uint32_t parity) {
    asm volatile(
        "{\n\t"
        ".reg .pred P1;\n\t"
        "WAITLOOP%=:\n\t"
        "mbarrier.try_wait.parity.acquire.cluster.shared::cta.b64 P1, [%0], %1, 0x989680;\n\t"
        "@P1 bra WAITDONE%=;\n\t"
        "bra WAITLOOP%=;\n\t"
        "WAITDONE%=:\n\t"
        "}"
        :: "r"(a), "r"(parity) : "memory");
}
__device__ __forceinline__ void cluster_sync_all() {
    asm volatile("barrier.cluster.arrive.aligned;" ::: "memory");
    asm volatile("barrier.cluster.wait.aligned;" ::: "memory");
}
__device__ __forceinline__ uint32_t my_ctarank() {
    uint32_t r;
    asm("mov.u32 %0, %%cluster_ctarank;" : "=r"(r));
    return r;
}

// ---------------- exact 1.5-entmax over 32 values, one per lane ----------------
__device__ __forceinline__ float entmax15_warp(float z, int lane) {
    const unsigned F = 0xffffffffu;
    float x = 0.5f * z;
    float m = x;
#pragma unroll
    for (int o = 16; o > 0; o >>= 1) m = fmaxf(m, __shfl_xor_sync(F, m, o));
    x -= m;
    float v = x;
#pragma unroll
    for (int k = 2; k <= 32; k <<= 1) {
#pragma unroll
        for (int j = k >> 1; j > 0; j >>= 1) {
            float o = __shfl_xor_sync(F, v, j);
            bool up = ((lane & k) == 0);
            if (((lane & j) == 0) == up) v = fminf(v, o);
            else                         v = fmaxf(v, o);
        }
    }
    float zs = __shfl_sync(F, v, 31 - lane);   // descending
    float s = zs, s2 = zs * zs;
#pragma unroll
    for (int d = 1; d < 32; d <<= 1) {
        float t1 = __shfl_up_sync(F, s, d);
        float t2 = __shfl_up_sync(F, s2, d);
        if (lane >= d) { s += t1; s2 += t2; }
    }
    float k1     = (float)(lane + 1);
    float mean   = s / k1;
    float meansq = s2 / k1;
    float ss     = k1 * (meansq - mean * mean);
    float delta  = (1.0f - ss) / k1;
    float tau    = mean - sqrtf(fmaxf(delta, 0.0f));
    unsigned bal = __ballot_sync(F, tau <= zs);
    int support  = __popc(bal) - 1;
    float tau_star = __shfl_sync(F, tau, support);
    float p = fmaxf(x - tau_star, 0.0f);
    return p * p;
}

// ---------------- SGEMM: C[M,N] = A[M,K] @ B[N,K]^T ----------------
template <int MODE>
__global__ void __launch_bounds__(256)
sgemm(const float* __restrict__ Aext, const float* __restrict__ Bmat,
      float* __restrict__ Cout, int M, int N, int K)
{
    __shared__ float As[8 * 128];
    __shared__ float Bs[8 * 128];

    const int tid = threadIdx.x;
    const int bm = blockIdx.y * 128;
    const int bn = blockIdx.x * 128;
    const int lrow = tid >> 1;
    const int lk   = (tid & 1) * 4;
    const int tx = tid & 15;
    const int ty = tid >> 4;

    const float* A = (MODE == 0) ? Aext : ((MODE == 1) ? g_xproj : g_hs);

    float acc[8][8];
#pragma unroll
    for (int i = 0; i < 8; i++)
#pragma unroll
        for (int j = 0; j < 8; j++) acc[i][j] = 0.0f;

    for (int kt = 0; kt < K; kt += 8) {
        float4 av = *(const float4*)(A + (size_t)(bm + lrow) * K + kt + lk);
        if (MODE == 2) {
            float4 sv = *(const float4*)(g_siluz + (size_t)(bm + lrow) * K + kt + lk);
            av.x *= sv.x; av.y *= sv.y; av.z *= sv.z; av.w *= sv.w;
        }
        As[(lk + 0) * 128 + lrow] = av.x;
        As[(lk + 1) * 128 + lrow] = av.y;
        As[(lk + 2) * 128 + lrow] = av.z;
        As[(lk + 3) * 128 + lrow] = av.w;
        float4 bv = *(const float4*)(Bmat + (size_t)(bn + lrow) * K + kt + lk);
        Bs[(lk + 0) * 128 + lrow] = bv.x;
        Bs[(lk + 1) * 128 + lrow] = bv.y;
        Bs[(lk + 2) * 128 + lrow] = bv.z;
        Bs[(lk + 3) * 128 + lrow] = bv.w;
        __syncthreads();
#pragma unroll
        for (int kk = 0; kk < 8; kk++) {
            float af[8], bf[8];
            *(float4*)(af + 0) = *(const float4*)(As + kk * 128 + ty * 8 + 0);
            *(float4*)(af + 4) = *(const float4*)(As + kk * 128 + ty * 8 + 4);
            *(float4*)(bf + 0) = *(const float4*)(Bs + kk * 128 + tx * 8 + 0);
            *(float4*)(bf + 4) = *(const float4*)(Bs + kk * 128 + tx * 8 + 4);
#pragma unroll
            for (int i = 0; i < 8; i++)
#pragma unroll
                for (int j = 0; j < 8; j++)
                    acc[i][j] = fmaf(af[i], bf[j], acc[i][j]);
        }
        __syncthreads();
    }

#pragma unroll
    for (int i = 0; i < 8; i++) {
        const size_t m = (size_t)(bm + ty * 8 + i);
#pragma unroll
        for (int j = 0; j < 8; j++) {
            const int gn = bn + tx * 8 + j;
            float v = acc[i][j];
            if (MODE == 0) {
                if (gn < DDIM) g_xproj[m * DDIM + gn] = siluf(v);
                else           g_siluz[m * DDIM + (gn - DDIM)] = siluf(v);
            } else if (MODE == 1) {
                g_xw[m * DDIM + gn] = v;
            } else {
                Cout[m * DDIM + gn] = v;
            }
        }
    }
}

// ---------------- shared-memory layout (float offsets) ----------------
#define BARS_F 0      // 2 x u64 mbarriers (bar0 @ +0B, bar1 @ +8B)
#define RBUF_F 4      // [CPB][32]  r-score partials
#define EX2_F  516    // [CPB][64]  h_new slice (0:32) + w partials (32:64)
#define TAPE_F 1540   // [32][33]
#define WORK_F 2596   // [512]
#define HPRE_F 3108   // [32]
#define HNEW_F 3140   // [32]
#define BV_F   3172   // [32]
#define WVAL_F 3204   // [32]
#define RPS_F  3236   // [32]
#define SRC_F  3268   // [64] staging for phase-B send
#define WH_F   3332   // [32*512]
#define WW_F   (WH_F + SLICE*DDIM)
#define SCAN_SMEM_F (WW_F + SLICE*DDIM)

// ---------------- dual-memory scan: 16-CTA cluster per batch ----------------
__global__ void __cluster_dims__(CPB, 1, 1) __launch_bounds__(SCAN_THREADS, 1)
scan_kernel(const float* __restrict__ W_h, const float* __restrict__ W_write,
            const float* __restrict__ b_h, float* __restrict__ dout)
{
    extern __shared__ float sm[];
    float* rbuf   = sm + RBUF_F;
    float* ex2    = sm + EX2_F;
    float* tape_s = sm + TAPE_F;
    float* work_s = sm + WORK_F;
    float* hpre_s = sm + HPRE_F;
    float* hnew_s = sm + HNEW_F;
    float* bv_s   = sm + BV_F;
    float* wval_s = sm + WVAL_F;
    float* rp_s   = sm + RPS_F;
    float* src64  = sm + SRC_F;
    float* Wh_s   = sm + WH_F;
    float* Ww_s   = sm + WW_F;

    const int tid  = threadIdx.x;
    const int wid  = tid >> 5;
    const int lane = tid & 31;
    const uint32_t c = my_ctarank();            // 0..15 within cluster
    const int b      = blockIdx.x / CPB;        // batch
    const int dbase  = (int)c * SLICE;
    const float scale = 0.044194173824159216f;  // 1/sqrt(512)
    const unsigned F = 0xffffffffu;
    const int o0 = 2 * wid, o1 = o0 + 1;

    const uint32_t smb  = smem_u32(sm);
    const uint32_t bar0 = smb;
    const uint32_t bar1 = smb + 8;
    const uint32_t rbuf_u = smb + RBUF_F * 4;
    const uint32_t ex2_u  = smb + EX2_F * 4;

    if (tid == 0) {
        mbar_init(bar0, CPB * 8);    // 8 sender-threads per source CTA
        mbar_init(bar1, CPB * 16);   // 16 sender-threads per source CTA
    }
    for (int i = tid; i < SLICE * DDIM / 4; i += SCAN_THREADS) {
        ((float4*)Wh_s)[i] = ((const float4*)(W_h     + (size_t)dbase * DDIM))[i];
        ((float4*)Ww_s)[i] = ((const float4*)(W_write + (size_t)dbase * DDIM))[i];
    }
    for (int i = tid; i < NSLOT * 33; i += SCAN_THREADS) tape_s[i] = 0.0f;
    for (int i = tid; i < DDIM; i += SCAN_THREADS) work_s[i] = 0.0f;
    __syncthreads();
    cluster_sync_all();

    float bh0 = 0.f, bh1 = 0.f, xw0 = 0.f, xw1 = 0.f;
    if (lane == 0) {
        bh0 = b_h[dbase + o0];
        bh1 = b_h[dbase + o1];
        size_t off0 = ((size_t)b * TSTEPS) * DDIM + dbase;
        xw0 = g_xw[off0 + o0];
        xw1 = g_xw[off0 + o1];
    }

    for (int t = 0; t < TSTEPS; t++) {
        const uint32_t parity = (uint32_t)(t & 1);

        // ---- Phase A: h_pre slice, r partials, broadcast ----
        {
            float acc0 = 0.0f, acc1 = 0.0f;
            const float* wr0 = Wh_s + o0 * DDIM;
            const float* wr1 = Wh_s + o1 * DDIM;
#pragma unroll
            for (int kk = 0; kk < 16; kk++) {
                int d = lane + kk * 32;
                float wv = work_s[d];
                acc0 = fmaf(wr0[d], wv, acc0);
                acc1 = fmaf(wr1[d], wv, acc1);
            }
#pragma unroll
            for (int o = 16; o > 0; o >>= 1) {
                acc0 += __shfl_xor_sync(F, acc0, o);
                acc1 += __shfl_xor_sync(F, acc1, o);
            }
            if (lane == 0) {
                hpre_s[o0] = acc0 + xw0 + bh0;
                hpre_s[o1] = acc1 + xw1 + bh1;
            }
        }
        __syncthreads();
        {
            float hp = hpre_s[lane];
            float rp0 = tape_s[o0 * 33 + lane] * hp;
            float rp1 = tape_s[o1 * 33 + lane] * hp;
#pragma unroll
            for (int o = 16; o > 0; o >>= 1) {
                rp0 += __shfl_xor_sync(F, rp0, o);
                rp1 += __shfl_xor_sync(F, rp1, o);
            }
            if (lane == 0) { rp_s[o0] = rp0; rp_s[o1] = rp1; }
        }
        __syncthreads();
        if (tid < CPB * 8) {                      // 8 threads per peer
            uint32_t peer = (uint32_t)(tid >> 3);
            int idx = tid & 7;
            float4 v = ((const float4*)rp_s)[idx];
            uint32_t dst = mapa_u32(rbuf_u + (c * 32 + idx * 4) * 4, peer);
            st_cluster_f4(dst, v);
            mbar_arrive_cluster(mapa_u32(bar0, peer));
        }
        mbar_wait(bar0, parity);

        // ---- Phase B: reduce r, entmax(a), read, h_new, w partials, broadcast ----
        if (wid == 0) {
            float rs = 0.0f;
#pragma unroll
            for (int s = 0; s < CPB; s++) rs += rbuf[s * 32 + lane];
            rs *= scale;
            float a = entmax15_warp(rs, lane);
            float rd = 0.0f;
#pragma unroll
            for (int n = 0; n < NSLOT; n++)
                rd = fmaf(__shfl_sync(F, a, n), tape_s[n * 33 + lane], rd);
            float hn = tanhf(hpre_s[lane] + rd);
            hnew_s[lane] = hn;
            src64[lane] = hn;
        }
        __syncthreads();
        {
            float hv = hnew_s[lane];
            float wp0 = tape_s[o0 * 33 + lane] * hv;
            float wp1 = tape_s[o1 * 33 + lane] * hv;
#pragma unroll
            for (int o = 16; o > 0; o >>= 1) {
                wp0 += __shfl_xor_sync(F, wp0, o);
                wp1 += __shfl_xor_sync(F, wp1, o);
            }
            if (lane == 0) { src64[32 + o0] = wp0; src64[32 + o1] = wp1; }
        }
        __syncthreads();
        if (tid < CPB * 16) {                     // 16 threads per peer
            uint32_t peer = (uint32_t)(tid >> 4);
            int idx = tid & 15;
            float4 v = ((const float4*)src64)[idx];
            uint32_t dst = mapa_u32(ex2_u + (c * 64 + idx * 4) * 4, peer);
            st_cluster_f4(dst, v);
            mbar_arrive_cluster(mapa_u32(bar1, peer));
        }
        mbar_wait(bar1, parity);

        // ---- Phase C: gather h, entmax(b) || w_val matvec, tape update ----
        work_s[tid] = ex2[wid * 64 + lane];       // full h_new assembled
        if (lane == 0 && t + 1 < TSTEPS) {        // prefetch next xw
            size_t offn = ((size_t)b * TSTEPS + (t + 1)) * DDIM + dbase;
            xw0 = g_xw[offn + o0];
            xw1 = g_xw[offn + o1];
        }
        __syncthreads();
        if (wid == 0) {
            float ws = 0.0f;
#pragma unroll
            for (int s = 0; s < CPB; s++) ws += ex2[s * 64 + 32 + lane];
            ws *= scale;
            bv_s[lane] = entmax15_warp(ws, lane);
        } else if (wid >= 8) {
            int r0 = (wid - 8) * 4;
            float a0 = 0.f, a1 = 0.f, a2 = 0.f, a3 = 0.f;
            const float* w0 = Ww_s + (r0 + 0) * DDIM;
            const float* w1 = Ww_s + (r0 + 1) * DDIM;
            const float* w2 = Ww_s + (r0 + 2) * DDIM;
            const float* w3 = Ww_s + (r0 + 3) * DDIM;
#pragma unroll
            for (int kk = 0; kk < 16; kk++) {
                int d = lane + kk * 32;
                float hv = work_s[d];
                a0 = fmaf(w0[d], hv, a0);
                a1 = fmaf(w1[d], hv, a1);
                a2 = fmaf(w2[d], hv, a2);
                a3 = fmaf(w3[d], hv, a3);
            }
#pragma unroll
            for (int o = 16; o > 0; o >>= 1) {
                a0 += __shfl_xor_sync(F, a0, o);
                a1 += __shfl_xor_sync(F, a1, o);
                a2 += __shfl_xor_sync(F, a2, o);
                a3 += __shfl_xor_sync(F, a3, o);
            }
            if (lane == 0) {
                wval_s[r0 + 0] = a0; wval_s[r0 + 1] = a1;
                wval_s[r0 + 2] = a2; wval_s[r0 + 3] = a3;
            }
        }
        __syncthreads();
#pragma unroll
        for (int it = 0; it < 2; it++) {
            int i = tid + it * SCAN_THREADS;
            int n = i >> 5, d2 = i & 31;
            float tv = tape_s[n * 33 + d2];
            tape_s[n * 33 + d2] = fmaf(bv_s[n], wval_s[d2] - tv, tv);
        }
        if (tid < SLICE)
            g_hs[((size_t)b * TSTEPS + t) * DDIM + dbase + tid] = hnew_s[tid];
        __syncthreads();
    }

    // ---- final outputs: tape_f and work_f ----
    const size_t TAPE_OFF = (size_t)BATCH * TSTEPS * DDIM;
    const size_t WORK_OFF = TAPE_OFF + (size_t)BATCH * NSLOT * DDIM;
#pragma unroll
    for (int it = 0; it < 2; it++) {
        int i = tid + it * SCAN_THREADS;
        int n = i >> 5, d2 = i & 31;
        dout[TAPE_OFF + ((size_t)b * NSLOT + n) * DDIM + dbase + d2] = tape_s[n * 33 + d2];
    }
    if (tid < SLICE)
        dout[WORK_OFF + (size_t)b * DDIM + dbase + tid] = work_s[dbase + tid];

    cluster_sync_all();   // no CTA exits while peers might still touch its SMEM
}

// ---------------- launcher ----------------
extern "C" void kernel_launch(void* const* d_in, const int* in_sizes, int n_in,
                              void* d_out, int out_size)
{
    const float* x       = (const float*)d_in[0];
    const float* W_in    = (const float*)d_in[1];
    const float* W_out   = (const float*)d_in[2];
    const float* W_h     = (const float*)d_in[3];
    const float* W_x     = (const float*)d_in[4];
    const float* b_h     = (const float*)d_in[5];
    const float* W_write = (const float*)d_in[6];
    float* out = (float*)d_out;

    const int scan_smem = SCAN_SMEM_F * (int)sizeof(float);
    cudaFuncSetAttribute(scan_kernel, cudaFuncAttributeMaxDynamicSharedMemorySize, scan_smem);
    cudaFuncSetAttribute(scan_kernel, cudaFuncAttributeNonPortableClusterSizeAllowed, 1);

    dim3 blk(256);
    sgemm<0><<<dim3(1024 / 128, MROWS / 128), blk>>>(x, W_in, nullptr, MROWS, 1024, DDIM);
    sgemm<1><<<dim3(DDIM / 128, MROWS / 128), blk>>>(nullptr, W_x, nullptr, MROWS, DDIM, DDIM);
    scan_kernel<<<BATCH * CPB, SCAN_THREADS, scan_smem>>>(W_h, W_write, b_h, out);
    sgemm<2><<<dim3(DDIM / 128, MROWS / 128), blk>>>(nullptr, W_out, out, MROWS, DDIM, DDIM);
}